// round 2
// baseline (speedup 1.0000x reference)
#include <cuda_runtime.h>

// Problem constants (fixed shapes: B=2, C=3, H=320, W=480)
#define HH   320
#define WW   480
#define BB   2
#define HWP  (HH * WW)          // 153600
#define NPIX (BB * HWP)         // 307200
#define SPAN 11
#define NOFF 23
#define NOFF2 (NOFF * NOFF)     // 529

#define RGN_ROWS 2
#define RGN_PIX  (RGN_ROWS * WW)   // 960
#define NREG     (HH / RGN_ROWS)   // 160 regions per batch
#define SRCW     (WW + 2 * SPAN)   // 502 (halo columns)

// ---------------- scratch (static device globals; no allocation) ------------
__device__ float4 g_img[NPIX];        // (r, g, b, m_dst)
__device__ float4 g_yh[NPIX];         // (yh0, yh1, yh2, unused)
__device__ float  g_wp[NPIX];         // src * (1 - dst)  (binary)
__device__ float  g_M[HWP];           // sum over batch of m_dst
__device__ float  g_rps[HH][WW + 1];  // row prefix sums of g_M
__device__ float  g_num[NOFF2];
__device__ float  g_den[NOFF2];
__device__ float  g_ce;

// ---------------- helpers ----------------------------------------------------
__device__ __forceinline__ float warpReduceSum(float v) {
#pragma unroll
    for (int o = 16; o > 0; o >>= 1)
        v += __shfl_xor_sync(0xffffffffu, v, o);
    return v;
}

__device__ __forceinline__ float blockReduceSum(float v) {
    __shared__ float sh[32];
    int lane = threadIdx.x & 31;
    int wid  = threadIdx.x >> 5;
    v = warpReduceSum(v);
    if (lane == 0) sh[wid] = v;
    __syncthreads();
    int nw = (blockDim.x + 31) >> 5;
    v = (wid == 0 && lane < nw) ? sh[lane] : 0.0f;
    if (wid == 0) v = warpReduceSum(v);
    return v;
}

// ---------------- kernel 0: zero accumulators --------------------------------
__global__ void k_zero() {
    int t = threadIdx.x;
    if (t < NOFF2) g_num[t] = 0.0f;
    if (t == NOFF2) g_ce = 0.0f;
}

// ---------------- kernel 1: softmax/CE/pack ----------------------------------
__global__ void k_prep(const float* __restrict__ logit,
                       const float* __restrict__ image,
                       const float* __restrict__ src,
                       const float* __restrict__ dst,
                       const int*   __restrict__ tgt) {
    int idx = blockIdx.x * blockDim.x + threadIdx.x;
    float prod = 0.0f;
    if (idx < HWP) {
        float Msum = 0.0f, ceSum = 0.0f, dstSum = 0.0f;
#pragma unroll
        for (int b = 0; b < BB; b++) {
            int cb = b * 3 * HWP + idx;
            float l0 = logit[cb], l1 = logit[cb + HWP], l2 = logit[cb + 2 * HWP];
            float m  = fmaxf(l0, fmaxf(l1, l2));
            float e0 = __expf(l0 - m), e1 = __expf(l1 - m), e2 = __expf(l2 - m);
            float s  = e0 + e1 + e2;
            float inv = 1.0f / s;

            int   t  = tgt[b * HWP + idx];
            float lt = (t == 0) ? l0 : ((t == 1) ? l1 : l2);
            float ce = m + __logf(s) - lt;

            float sv   = src[b * HWP + idx];
            float dv   = dst[b * HWP + idx];
            float mdst = 1.0f - dv;
            float wp   = sv * mdst;

            float i0 = image[cb], i1 = image[cb + HWP], i2 = image[cb + 2 * HWP];
            g_img[b * HWP + idx] = make_float4(i0, i1, i2, mdst);
            g_yh[b * HWP + idx]  = make_float4(e0 * inv, e1 * inv, e2 * inv, 0.0f);
            g_wp[b * HWP + idx]  = wp;

            ceSum  += ce;
            dstSum += dv;
            Msum   += mdst;
        }
        g_M[idx] = Msum;
        prod = ceSum * dstSum;
    }
    float bs = blockReduceSum(prod);
    if (threadIdx.x == 0) atomicAdd(&g_ce, bs);
}

// ---------------- kernel 2a: row prefix sums of g_M ---------------------------
__global__ void k_rps() {
    __shared__ float s[WW];
    int i   = blockIdx.x;
    int tid = threadIdx.x;   // 512 threads
    if (tid < WW) s[tid] = g_M[i * WW + tid];
    __syncthreads();
#pragma unroll
    for (int off = 1; off < WW; off <<= 1) {
        float v = 0.0f;
        if (tid >= off && tid < WW) v = s[tid - off];
        __syncthreads();
        if (tid < WW) s[tid] += v;
        __syncthreads();
    }
    if (tid == 0) g_rps[i][0] = 0.0f;
    if (tid < WW) g_rps[i][tid + 1] = s[tid];
}

// ---------------- kernel 2b: denominators via rectangle sums ------------------
__global__ void k_den() {
    int d  = blockIdx.x;
    int dx = d / NOFF - SPAN;
    int dy = d % NOFF - SPAN;
    int r0 = (dx < 0) ? -dx : 0;
    int r1 = (dx > 0) ? HH - dx : HH;
    int c0 = (dy < 0) ? -dy : 0;
    int c1 = (dy > 0) ? WW - dy : WW;
    float s = 0.0f;
    for (int i = r0 + threadIdx.x; i < r1; i += blockDim.x)
        s += g_rps[i][c1] - g_rps[i][c0];
    float tot = blockReduceSum(s);
    if (threadIdx.x == 0) g_den[d] = tot;
}

// ---------------- kernel 3: numerators ----------------------------------------
// Block = (region of 2 dest rows in one batch) x (one dx). Source rows staged
// in smem with halo; validity folded into Yq.w. Each thread keeps 22 register
// accumulators (one per dy) reduced once per block. wp is binary -> active
// pixels contribute with weight exactly 1.
__global__ void __launch_bounds__(256) k_num() {
    __shared__ float4 sI[RGN_ROWS][SRCW];
    __shared__ float4 sY[RGN_ROWS][SRCW];
    __shared__ float  skxy[NOFF];
    __shared__ unsigned short slist[RGN_PIX];
    __shared__ int s_woff[8];
    __shared__ int s_cnt;

    int tid  = threadIdx.x;
    int lane = tid & 31;
    int wid  = tid >> 5;

    int rb = blockIdx.x;                 // 0..319
    int b  = rb / NREG;
    int i0 = (rb - b * NREG) * RGN_ROWS;
    int dxi = blockIdx.y;                // 0..21 (dx != 0)
    int dx  = (dxi < SPAN) ? dxi - SPAN : dxi - SPAN + 1;

    if (tid < NOFF) {
        int dy = tid - SPAN;
        skxy[tid] = __expf((float)(dx * dx + dy * dy) * (-1.0f / 72.0f));
    }
    if (tid == 0) s_cnt = 0;

    int bHW  = b * HWP;
    int base = bHW + i0 * WW;

    // Stage source rows (i0+dx, i0+1+dx) with +/-SPAN column halo.
    for (int t = tid; t < RGN_ROWS * SRCW; t += 256) {
        int r  = t / SRCW;
        int c  = t - r * SRCW;
        int si = i0 + r + dx;
        int sj = c - SPAN;
        bool v = (si >= 0) && (si < HH) && (sj >= 0) && (sj < WW);
        float4 iq = make_float4(0.f, 0.f, 0.f, 0.f);
        float4 yq = make_float4(0.f, 0.f, 0.f, 0.f);
        if (v) {
            int q = bHW + si * WW + sj;
            iq = g_img[q];
            yq = g_yh[q];
        }
        yq.w = v ? 1.0f : 0.0f;
        sI[r][c] = iq;
        sY[r][c] = yq;
    }
    __syncthreads();

    // Ordered compaction of active dest pixels in this region.
    for (int chunk = 0; chunk < RGN_PIX; chunk += 256) {
        int t = chunk + tid;
        bool a = (t < RGN_PIX) && (g_wp[base + t] > 0.0f);
        unsigned bal = __ballot_sync(0xffffffffu, a);
        if (lane == 0) s_woff[wid] = __popc(bal);
        __syncthreads();
        if (tid == 0) {
            int acc = s_cnt;
#pragma unroll
            for (int w = 0; w < 8; w++) { int c = s_woff[w]; s_woff[w] = acc; acc += c; }
            s_cnt = acc;
        }
        __syncthreads();
        if (a) {
            int pos = s_woff[wid] + __popc(bal & ((1u << lane) - 1u));
            slist[pos] = (unsigned short)t;
        }
        __syncthreads();
    }
    int cnt = s_cnt;

    float acc[NOFF];
#pragma unroll
    for (int k = 0; k < NOFF; k++) acc[k] = 0.0f;

    for (int t = tid; t < cnt; t += 256) {
        int loc = slist[t];
        int r   = loc / WW;          // 0 or 1
        int j   = loc - r * WW;
        int p   = base + loc;
        float4 I = g_img[p];
        float4 Y = g_yh[p];
#pragma unroll
        for (int k = 0; k < NOFF; k++) {
            if (k == SPAN) continue;     // dy == 0 skipped
            float4 Iq = sI[r][j + k];
            float4 Yq = sY[r][j + k];
            float d0 = I.x - Iq.x, d1 = I.y - Iq.y, d2 = I.z - Iq.z;
            float ssd  = d0 * d0 + d1 * d1 + d2 * d2;
            float krgb = __expf(-50.0f * ssd);
            float dot  = Y.x * Yq.x + Y.y * Yq.y + Y.z * Yq.z;
            float tv   = (1.0f - dot) * Yq.w;        // validity masked here
            acc[k] += (krgb + skxy[k]) * tv;
        }
    }

#pragma unroll
    for (int k = 0; k < NOFF; k++) {
        if (k == SPAN) continue;
        float v = warpReduceSum(acc[k]);
        if (lane == 0) atomicAdd(&g_num[(dx + SPAN) * NOFF + k], v);
    }
}

// ---------------- kernel 4: finalize ------------------------------------------
__global__ void k_final(float* __restrict__ out) {
    float s = 0.0f;
    for (int d = threadIdx.x; d < NOFF2; d += blockDim.x) {
        int dx = d / NOFF - SPAN;
        int dy = d % NOFF - SPAN;
        if (dx != 0 && dy != 0) s += g_num[d] / g_den[d];
    }
    float tot = blockReduceSum(s);
    if (threadIdx.x == 0) {
        float l_ce   = g_ce * (1.0f / ((float)BB * BB * HWP));
        float l_gcrf = tot * (1.0f / (float)NOFF2);
        out[0] = l_ce + 0.15f * l_gcrf;
    }
}

// ---------------- launch --------------------------------------------------------
extern "C" void kernel_launch(void* const* d_in, const int* in_sizes, int n_in,
                              void* d_out, int out_size) {
    const float* logit = (const float*)d_in[0];
    const float* image = (const float*)d_in[1];
    const float* srcm  = (const float*)d_in[2];
    const float* dstm  = (const float*)d_in[3];
    const int*   tgt   = (const int*)d_in[4];
    float* out = (float*)d_out;

    k_zero<<<1, NOFF2 + 32>>>();
    k_prep<<<HWP / 256, 256>>>(logit, image, srcm, dstm, tgt);
    k_rps<<<HH, 512>>>();
    k_den<<<NOFF2, 128>>>();
    k_num<<<dim3(BB * NREG, 2 * SPAN), 256>>>();
    k_final<<<1, 256>>>(out);
}

// round 3
// speedup vs baseline: 2.7109x; 2.7109x over previous
#include <cuda_runtime.h>
#include <cuda_fp16.h>

// Fixed shapes: B=2, C=3, H=320, W=480
#define HH   320
#define WW   480
#define BB   2
#define HWP  (HH * WW)          // 153600
#define NPIX (BB * HWP)         // 307200
#define SPAN 11
#define NOFF 23
#define NOFF2 (NOFF * NOFF)     // 529

#define PADH (HH + 2 * SPAN)    // 342
#define PADW 512                // padded row stride (>= 480+22, aligned)
#define PADSZ (PADH * PADW)     // 175104 per batch

// ---------------- scratch (static device globals) ----------------------------
__device__ float4 g_pix[BB * PADSZ];  // packed {h2(r,g), h2(b,y0), h2(y1,y2), valid}
__device__ float  g_wp[NPIX];         // src * (1 - dst)  (binary, dest mask)
__device__ float  g_M[HWP];           // sum over batch of (1 - dst)
__device__ float  g_rps[HH][WW + 1];  // row prefix sums of g_M
__device__ int    g_act[NPIX];        // compacted padded-indices of active pixels
__device__ int    g_nact;
__device__ float  g_num[NOFF2];
__device__ float  g_den[NOFF2];
__device__ float  g_ce;

// ---------------- helpers ----------------------------------------------------
__device__ __forceinline__ float warpReduceSum(float v) {
#pragma unroll
    for (int o = 16; o > 0; o >>= 1)
        v += __shfl_xor_sync(0xffffffffu, v, o);
    return v;
}

__device__ __forceinline__ float blockReduceSum(float v) {
    __shared__ float sh[32];
    int lane = threadIdx.x & 31;
    int wid  = threadIdx.x >> 5;
    v = warpReduceSum(v);
    if (lane == 0) sh[wid] = v;
    __syncthreads();
    int nw = (blockDim.x + 31) >> 5;
    v = (wid == 0 && lane < nw) ? sh[lane] : 0.0f;
    if (wid == 0) v = warpReduceSum(v);
    return v;
}

__device__ __forceinline__ float pack2(float a, float b) {
    __half2 h = __floats2half2_rn(a, b);
    unsigned u = *reinterpret_cast<unsigned*>(&h);
    return __uint_as_float(u);
}
__device__ __forceinline__ float2 up2(float w) {
    unsigned u = __float_as_uint(w);
    __half2 h = *reinterpret_cast<__half2*>(&u);
    return __half22float2(h);
}

// ---------------- kernel 0: clear padded buffer + accumulators ----------------
__global__ void k_clear() {
    int t = blockIdx.x * blockDim.x + threadIdx.x;
    if (t < BB * PADSZ) g_pix[t] = make_float4(0.f, 0.f, 0.f, 0.f);
    if (t < NOFF2) g_num[t] = 0.0f;
    if (t == NOFF2)     g_ce = 0.0f;
    if (t == NOFF2 + 1) g_nact = 0;
}

// ---------------- kernel 1: softmax/CE/pack into padded halo array ------------
__global__ void k_prep(const float* __restrict__ logit,
                       const float* __restrict__ image,
                       const float* __restrict__ src,
                       const float* __restrict__ dst,
                       const int*   __restrict__ tgt) {
    int idx = blockIdx.x * blockDim.x + threadIdx.x;
    float prod = 0.0f;
    if (idx < HWP) {
        int i = idx / WW;
        int j = idx - i * WW;
        int pidx = (i + SPAN) * PADW + (j + SPAN);
        float Msum = 0.0f, ceSum = 0.0f, dstSum = 0.0f;
#pragma unroll
        for (int b = 0; b < BB; b++) {
            int cb = b * 3 * HWP + idx;
            float l0 = logit[cb], l1 = logit[cb + HWP], l2 = logit[cb + 2 * HWP];
            float m  = fmaxf(l0, fmaxf(l1, l2));
            float e0 = __expf(l0 - m), e1 = __expf(l1 - m), e2 = __expf(l2 - m);
            float s  = e0 + e1 + e2;
            float inv = 1.0f / s;

            int   t  = tgt[b * HWP + idx];
            float lt = (t == 0) ? l0 : ((t == 1) ? l1 : l2);
            float ce = m + __logf(s) - lt;

            float sv   = src[b * HWP + idx];
            float dv   = dst[b * HWP + idx];
            float mdst = 1.0f - dv;

            float i0 = image[cb], i1 = image[cb + HWP], i2 = image[cb + 2 * HWP];
            float y0 = e0 * inv, y1 = e1 * inv, y2 = e2 * inv;

            float4 v;
            v.x = pack2(i0, i1);
            v.y = pack2(i2, y0);
            v.z = pack2(y1, y2);
            v.w = 1.0f;                       // valid flag (halo stays 0)
            g_pix[b * PADSZ + pidx] = v;
            g_wp[b * HWP + idx] = sv * mdst;

            ceSum  += ce;
            dstSum += dv;
            Msum   += mdst;
        }
        g_M[idx] = Msum;
        prod = ceSum * dstSum;
    }
    float bs = blockReduceSum(prod);
    if (threadIdx.x == 0) atomicAdd(&g_ce, bs);
}

// ---------------- kernel 2: locally-ordered compaction ------------------------
// Each 256-thread block compacts its 256 pixels in order, grabs a base via one
// atomic. Within-block spatial order => warp lanes in k_num are adjacent.
__global__ void k_compact() {
    __shared__ int s_w[8];
    __shared__ int s_base;
    int tid  = threadIdx.x;
    int lane = tid & 31;
    int wid  = tid >> 5;
    int p    = blockIdx.x * 256 + tid;          // < NPIX exactly

    bool a = g_wp[p] > 0.0f;
    unsigned bal = __ballot_sync(0xffffffffu, a);
    if (lane == 0) s_w[wid] = __popc(bal);
    __syncthreads();
    if (tid == 0) {
        int acc = 0;
#pragma unroll
        for (int w = 0; w < 8; w++) { int c = s_w[w]; s_w[w] = acc; acc += c; }
        s_base = atomicAdd(&g_nact, acc);
    }
    __syncthreads();
    if (a) {
        int pos = s_base + s_w[wid] + __popc(bal & ((1u << lane) - 1u));
        int b   = p / HWP;
        int rem = p - b * HWP;
        int i   = rem / WW;
        int j   = rem - i * WW;
        g_act[pos] = b * PADSZ + (i + SPAN) * PADW + (j + SPAN);
    }
}

// ---------------- kernel 3a: row prefix sums of g_M ---------------------------
__global__ void k_rps() {
    __shared__ float s[WW];
    int i   = blockIdx.x;
    int tid = threadIdx.x;   // 512 threads
    if (tid < WW) s[tid] = g_M[i * WW + tid];
    __syncthreads();
#pragma unroll
    for (int off = 1; off < WW; off <<= 1) {
        float v = 0.0f;
        if (tid >= off && tid < WW) v = s[tid - off];
        __syncthreads();
        if (tid < WW) s[tid] += v;
        __syncthreads();
    }
    if (tid == 0) g_rps[i][0] = 0.0f;
    if (tid < WW) g_rps[i][tid + 1] = s[tid];
}

// ---------------- kernel 3b: denominators via rectangle sums ------------------
__global__ void k_den() {
    int d  = blockIdx.x;
    int dx = d / NOFF - SPAN;
    int dy = d % NOFF - SPAN;
    int r0 = (dx < 0) ? -dx : 0;
    int r1 = (dx > 0) ? HH - dx : HH;
    int c0 = (dy < 0) ? -dy : 0;
    int c1 = (dy > 0) ? WW - dy : WW;
    float s = 0.0f;
    for (int i = r0 + threadIdx.x; i < r1; i += blockDim.x)
        s += g_rps[i][c1] - g_rps[i][c0];
    float tot = blockReduceSum(s);
    if (threadIdx.x == 0) g_den[d] = tot;
}

// ---------------- kernel 4: numerators ----------------------------------------
// Thread = one active dest pixel; blockIdx.y selects dx half (11 values each).
// One 16B gather per pair; acc[23] registers per dx, reduced after the dy loop.
__global__ void __launch_bounds__(256) k_num() {
    __shared__ float s_kdy[NOFF];
    int tid  = threadIdx.x;
    int lane = tid & 31;

    if (tid < NOFF) {
        int dy = tid - SPAN;
        s_kdy[tid] = __expf((float)(dy * dy) * (-1.0f / 72.0f));
    }
    __syncthreads();

    int n    = g_nact;
    int gtid = blockIdx.x * 256 + tid;
    if ((gtid & ~31) >= n) return;                 // whole-warp exit only

    bool  act  = gtid < n;
    float wval = act ? 1.0f : 0.0f;
    int   idx  = g_act[act ? gtid : (gtid & ~31)]; // safe dummy for tail lanes

    float4 pv = g_pix[idx];
    float2 prg = up2(pv.x);
    float2 pby = up2(pv.y);
    float2 pyz = up2(pv.z);
    float rp = prg.x, gp = prg.y, bp = pby.x;
    float y0p = pby.y, y1p = pyz.x, y2p = pyz.y;

    int dx0 = (blockIdx.y == 0) ? -SPAN : 1;

#pragma unroll 1
    for (int t = 0; t < SPAN; t++) {
        int dx = dx0 + t;
        float kxr = __expf((float)(dx * dx) * (-1.0f / 72.0f));
        int qbase = idx + dx * PADW;

        float acc[NOFF];
#pragma unroll
        for (int k = 0; k < NOFF; k++) acc[k] = 0.0f;

#pragma unroll
        for (int k = 0; k < NOFF; k++) {
            if (k == SPAN) continue;               // dy == 0 skipped
            float4 v = g_pix[qbase + (k - SPAN)];
            float2 qrg = up2(v.x);
            float2 qby = up2(v.y);
            float2 qyz = up2(v.z);
            float dr = rp - qrg.x, dg = gp - qrg.y, db = bp - qby.x;
            float ssd  = dr * dr + dg * dg + db * db;
            float krgb = __expf(-50.0f * ssd);
            float dot  = y0p * qby.y + y1p * qyz.x + y2p * qyz.y;
            float tv   = fmaf(-dot, v.w, v.w);     // (1 - dot) * valid
            float kxy  = kxr * s_kdy[k];
            acc[k] = fmaf(krgb + kxy, tv, acc[k]);
        }

        int rowbin = (dx + SPAN) * NOFF;
#pragma unroll
        for (int k = 0; k < NOFF; k++) {
            if (k == SPAN) continue;
            float v = warpReduceSum(acc[k] * wval);
            if (lane == 0) atomicAdd(&g_num[rowbin + k], v);
        }
    }
}

// ---------------- kernel 5: finalize ------------------------------------------
__global__ void k_final(float* __restrict__ out) {
    float s = 0.0f;
    for (int d = threadIdx.x; d < NOFF2; d += blockDim.x) {
        int dx = d / NOFF - SPAN;
        int dy = d % NOFF - SPAN;
        if (dx != 0 && dy != 0) s += g_num[d] / g_den[d];
    }
    float tot = blockReduceSum(s);
    if (threadIdx.x == 0) {
        float l_ce   = g_ce * (1.0f / ((float)BB * BB * HWP));
        float l_gcrf = tot * (1.0f / (float)NOFF2);
        out[0] = l_ce + 0.15f * l_gcrf;
    }
}

// ---------------- launch --------------------------------------------------------
extern "C" void kernel_launch(void* const* d_in, const int* in_sizes, int n_in,
                              void* d_out, int out_size) {
    const float* logit = (const float*)d_in[0];
    const float* image = (const float*)d_in[1];
    const float* srcm  = (const float*)d_in[2];
    const float* dstm  = (const float*)d_in[3];
    const int*   tgt   = (const int*)d_in[4];
    float* out = (float*)d_out;

    k_clear<<<(BB * PADSZ + 255) / 256, 256>>>();
    k_prep<<<(HWP + 255) / 256, 256>>>(logit, image, srcm, dstm, tgt);
    k_compact<<<NPIX / 256, 256>>>();
    k_rps<<<HH, 512>>>();
    k_den<<<NOFF2, 128>>>();
    k_num<<<dim3(NPIX / 256, 2), 256>>>();
    k_final<<<1, 256>>>(out);
}

// round 4
// speedup vs baseline: 9.3671x; 3.4553x over previous
#include <cuda_runtime.h>

// Fixed shapes: B=2, C=3, H=320, W=480
#define HH   320
#define WW   480
#define BB   2
#define HWP  (HH * WW)          // 153600
#define NPIX (BB * HWP)         // 307200
#define SPAN 11
#define NOFF 23
#define NOFF2 (NOFF * NOFF)     // 529

#define PADW 512                // padded row stride (power of 2)
#define PADH (HH + 2 * SPAN)    // 342
#define PADSZ (PADH * PADW)     // 175104 per batch (multiple of 512)

#define NUMX 48                 // x-blocks per dx slice in k_num

// ---------------- scratch (static device globals) ----------------------------
__device__ uint2 g_pix8[BB * PADSZ];  // {r|g<<8|b<<16, y0|y1<<8|y2<<16} u8 packed
__device__ float g_wp[NPIX];          // src * (1 - dst)  (binary dest-activity)
__device__ float g_M[HWP];            // sum over batch of (1 - dst)
__device__ float g_rps[HH][WW + 1];   // row prefix sums of g_M
__device__ int   g_act[NPIX];         // compacted padded indices of active pixels
__device__ int   g_nact;
__device__ float g_num[NOFF2];
__device__ float g_den[NOFF2];
__device__ float g_ce;

// ---------------- helpers ----------------------------------------------------
__device__ __forceinline__ float warpReduceSum(float v) {
#pragma unroll
    for (int o = 16; o > 0; o >>= 1)
        v += __shfl_xor_sync(0xffffffffu, v, o);
    return v;
}

__device__ __forceinline__ float blockReduceSum(float v) {
    __shared__ float sh[32];
    int lane = threadIdx.x & 31;
    int wid  = threadIdx.x >> 5;
    v = warpReduceSum(v);
    if (lane == 0) sh[wid] = v;
    __syncthreads();
    int nw = (blockDim.x + 31) >> 5;
    v = (wid == 0 && lane < nw) ? sh[lane] : 0.0f;
    if (wid == 0) v = warpReduceSum(v);
    return v;
}

// ---------------- kernel 0: zero small accumulators ----------------------------
__global__ void k_zero() {
    int t = threadIdx.x;
    if (t < NOFF2) g_num[t] = 0.0f;
    if (t == NOFF2)     g_ce = 0.0f;
    if (t == NOFF2 + 1) g_nact = 0;
}

// ---------------- kernel 1: softmax/CE/pack (u8) into padded array -------------
__global__ void k_prep(const float* __restrict__ logit,
                       const float* __restrict__ image,
                       const float* __restrict__ src,
                       const float* __restrict__ dst,
                       const int*   __restrict__ tgt) {
    int idx = blockIdx.x * blockDim.x + threadIdx.x;
    float prod = 0.0f;
    if (idx < HWP) {
        int i = idx / WW;
        int j = idx - i * WW;
        int pidx = (i + SPAN) * PADW + (j + SPAN);
        float Msum = 0.0f, ceSum = 0.0f, dstSum = 0.0f;
#pragma unroll
        for (int b = 0; b < BB; b++) {
            int cb = b * 3 * HWP + idx;
            float l0 = logit[cb], l1 = logit[cb + HWP], l2 = logit[cb + 2 * HWP];
            float m  = fmaxf(l0, fmaxf(l1, l2));
            float e0 = __expf(l0 - m), e1 = __expf(l1 - m), e2 = __expf(l2 - m);
            float s  = e0 + e1 + e2;
            float inv = 1.0f / s;

            int   t  = tgt[b * HWP + idx];
            float lt = (t == 0) ? l0 : ((t == 1) ? l1 : l2);
            float ce = m + __logf(s) - lt;

            float sv   = src[b * HWP + idx];
            float dv   = dst[b * HWP + idx];
            float mdst = 1.0f - dv;

            float i0 = image[cb], i1 = image[cb + HWP], i2 = image[cb + 2 * HWP];
            unsigned r8 = __float2uint_rn(i0 * 255.0f);
            unsigned g8 = __float2uint_rn(i1 * 255.0f);
            unsigned b8 = __float2uint_rn(i2 * 255.0f);

            float y0 = e0 * inv, y1 = e1 * inv;
            int y0q = (int)__float2uint_rn(y0 * 255.0f);
            int y1q = (int)__float2uint_rn(y1 * 255.0f);
            int y2q = 255 - y0q - y1q;
            if (y2q < 0) y2q = 0;

            uint2 v;
            v.x = r8 | (g8 << 8) | (b8 << 16);
            v.y = (unsigned)y0q | ((unsigned)y1q << 8) | ((unsigned)y2q << 16);
            g_pix8[b * PADSZ + pidx] = v;
            g_wp[b * HWP + idx] = sv * mdst;

            ceSum  += ce;
            dstSum += dv;
            Msum   += mdst;
        }
        g_M[idx] = Msum;
        prod = ceSum * dstSum;
    }
    float bs = blockReduceSum(prod);
    if (threadIdx.x == 0) atomicAdd(&g_ce, bs);
}

// ---------------- kernel 2: locally-ordered compaction -------------------------
__global__ void k_compact() {
    __shared__ int s_w[8];
    __shared__ int s_base;
    int tid  = threadIdx.x;
    int lane = tid & 31;
    int wid  = tid >> 5;
    int p    = blockIdx.x * 256 + tid;          // < NPIX exactly

    bool a = g_wp[p] > 0.0f;
    unsigned bal = __ballot_sync(0xffffffffu, a);
    if (lane == 0) s_w[wid] = __popc(bal);
    __syncthreads();
    if (tid == 0) {
        int acc = 0;
#pragma unroll
        for (int w = 0; w < 8; w++) { int c = s_w[w]; s_w[w] = acc; acc += c; }
        s_base = atomicAdd(&g_nact, acc);
    }
    __syncthreads();
    if (a) {
        int pos = s_base + s_w[wid] + __popc(bal & ((1u << lane) - 1u));
        int b   = p / HWP;
        int rem = p - b * HWP;
        int i   = rem / WW;
        int j   = rem - i * WW;
        g_act[pos] = b * PADSZ + (i + SPAN) * PADW + (j + SPAN);
    }
}

// ---------------- kernel 3a: row prefix sums of g_M ----------------------------
__global__ void k_rps() {
    __shared__ float s[WW];
    int i   = blockIdx.x;
    int tid = threadIdx.x;   // 512 threads
    if (tid < WW) s[tid] = g_M[i * WW + tid];
    __syncthreads();
#pragma unroll
    for (int off = 1; off < WW; off <<= 1) {
        float v = 0.0f;
        if (tid >= off && tid < WW) v = s[tid - off];
        __syncthreads();
        if (tid < WW) s[tid] += v;
        __syncthreads();
    }
    if (tid == 0) g_rps[i][0] = 0.0f;
    if (tid < WW) g_rps[i][tid + 1] = s[tid];
}

// ---------------- kernel 3b: denominators via rectangle sums -------------------
__global__ void k_den() {
    int d  = blockIdx.x;
    int dx = d / NOFF - SPAN;
    int dy = d % NOFF - SPAN;
    int r0 = (dx < 0) ? -dx : 0;
    int r1 = (dx > 0) ? HH - dx : HH;
    int c0 = (dy < 0) ? -dy : 0;
    int c1 = (dy > 0) ? WW - dy : WW;
    float s = 0.0f;
    for (int i = r0 + threadIdx.x; i < r1; i += blockDim.x)
        s += g_rps[i][c1] - g_rps[i][c0];
    float tot = blockReduceSum(s);
    if (threadIdx.x == 0) g_den[d] = tot;
}

// ---------------- kernel 4: numerators ------------------------------------------
// One dx per blockIdx.y; threads grid-stride the active list holding acc[23],
// reduce ONCE at thread end. Per pair: LDG.64 + vabsdiff4/dp4a integer SIMD.
__global__ void __launch_bounds__(256) k_num() {
    __shared__ float s_kxy[NOFF];

    int dxi = blockIdx.y;                       // 0..21
    int dx  = (dxi < SPAN) ? dxi - SPAN : dxi - SPAN + 1;

    if (threadIdx.x < NOFF) {
        int dy = threadIdx.x - SPAN;
        s_kxy[threadIdx.x] = __expf((float)(dx * dx + dy * dy) * (-1.0f / 72.0f));
    }
    __syncthreads();

    float acc[NOFF];
#pragma unroll
    for (int k = 0; k < NOFF; k++) acc[k] = 0.0f;

    const float KC  = (-50.0f / 65025.0f) * 1.44269504088896f;  // exp2 scale for ssd
    const float YC  = -1.0f / 65025.0f;

    int n = g_nact;
    int stride = gridDim.x * 256;
    for (int t = blockIdx.x * 256 + threadIdx.x; t < n; t += stride) {
        int idx = g_act[t];
        int r   = idx >> 9;                     // b*342 + padded row
        int rq  = r + dx;
        int rloc = rq - ((r >= PADH) ? PADH : 0);
        if ((unsigned)(rloc - SPAN) >= (unsigned)HH) continue;   // row invalid
        int pcol = idx & (PADW - 1);

        uint2 p = g_pix8[idx];
        const uint2* __restrict__ qrow = g_pix8 + (idx + dx * PADW);

#pragma unroll
        for (int k = 0; k < NOFF; k++) {
            if (k == SPAN) continue;            // dy == 0 skipped
            uint2 q = qrow[k - SPAN];
            unsigned d  = __vabsdiffu4(p.x, q.x);
            unsigned s2 = __dp4a(d, d, 0u);
            unsigned dp = __dp4a(p.y, q.y, 0u);
            float krgb = exp2f(__uint2float_rn(s2) * KC);
            float tv   = fmaf(__uint2float_rn(dp), YC, 1.0f);
            int   qc   = pcol + (k - SPAN);
            bool  ok   = (unsigned)(qc - SPAN) < (unsigned)WW;
            if (ok) acc[k] += (krgb + s_kxy[k]) * tv;
        }
    }

    int lane   = threadIdx.x & 31;
    int rowbin = (dx + SPAN) * NOFF;
#pragma unroll
    for (int k = 0; k < NOFF; k++) {
        if (k == SPAN) continue;
        float v = warpReduceSum(acc[k]);
        if (lane == 0) atomicAdd(&g_num[rowbin + k], v);
    }
}

// ---------------- kernel 5: finalize --------------------------------------------
__global__ void k_final(float* __restrict__ out) {
    float s = 0.0f;
    for (int d = threadIdx.x; d < NOFF2; d += blockDim.x) {
        int dx = d / NOFF - SPAN;
        int dy = d % NOFF - SPAN;
        if (dx != 0 && dy != 0) s += g_num[d] / g_den[d];
    }
    float tot = blockReduceSum(s);
    if (threadIdx.x == 0) {
        float l_ce   = g_ce * (1.0f / ((float)BB * BB * HWP));
        float l_gcrf = tot * (1.0f / (float)NOFF2);
        out[0] = l_ce + 0.15f * l_gcrf;
    }
}

// ---------------- launch ----------------------------------------------------------
extern "C" void kernel_launch(void* const* d_in, const int* in_sizes, int n_in,
                              void* d_out, int out_size) {
    const float* logit = (const float*)d_in[0];
    const float* image = (const float*)d_in[1];
    const float* srcm  = (const float*)d_in[2];
    const float* dstm  = (const float*)d_in[3];
    const int*   tgt   = (const int*)d_in[4];
    float* out = (float*)d_out;

    k_zero<<<1, NOFF2 + 32>>>();
    k_prep<<<(HWP + 255) / 256, 256>>>(logit, image, srcm, dstm, tgt);
    k_compact<<<NPIX / 256, 256>>>();
    k_rps<<<HH, 512>>>();
    k_den<<<NOFF2, 128>>>();
    k_num<<<dim3(NUMX, 2 * SPAN), 256>>>();
    k_final<<<1, 256>>>(out);
}

// round 5
// speedup vs baseline: 9.3766x; 1.0010x over previous
#include <cuda_runtime.h>

// Fixed shapes: B=2, C=3, H=320, W=480
#define HH   320
#define WW   480
#define BB   2
#define HWP  (HH * WW)          // 153600
#define NPIX (BB * HWP)         // 307200
#define SPAN 11
#define NOFF 23
#define NOFF2 (NOFF * NOFF)     // 529

#define PADW 512                // padded row stride (power of 2)
#define PADH (HH + 2 * SPAN)    // 342
#define PADSZ (PADH * PADW)     // 175104 per batch

#define NUMX 48                 // x-blocks per dx slice in k_num

// ---------------- scratch (static device globals) ----------------------------
__device__ uint2 g_pix8[BB * PADSZ];  // {r|g<<8|b<<16, y0|y1<<8|y2<<16 | halo<<24}
__device__ float g_wp[NPIX];          // src * (1 - dst)  (binary dest-activity)
__device__ float g_M[HWP];            // sum over batch of (1 - dst)
__device__ float g_rps[HH][WW + 1];   // row prefix sums of g_M
__device__ int   g_act[NPIX];         // compacted padded indices of active pixels
__device__ int   g_nact;
__device__ float g_num[NOFF2];
__device__ float g_den[NOFF2];
__device__ float g_ce;

// ---------------- helpers ----------------------------------------------------
__device__ __forceinline__ float warpReduceSum(float v) {
#pragma unroll
    for (int o = 16; o > 0; o >>= 1)
        v += __shfl_xor_sync(0xffffffffu, v, o);
    return v;
}

__device__ __forceinline__ float blockReduceSum(float v) {
    __shared__ float sh[32];
    int lane = threadIdx.x & 31;
    int wid  = threadIdx.x >> 5;
    v = warpReduceSum(v);
    if (lane == 0) sh[wid] = v;
    __syncthreads();
    int nw = (blockDim.x + 31) >> 5;
    v = (wid == 0 && lane < nw) ? sh[lane] : 0.0f;
    if (wid == 0) v = warpReduceSum(v);
    return v;
}

// ---------------- kernel 0: halo marker + zero accumulators --------------------
// Every cell gets {rgb=0, y=0xFF000000 (invalid marker)}. k_prep overwrites the
// interior afterwards, leaving the marker only on halo cells. Re-done each
// launch so replays are deterministic.
__global__ void k_zero() {
    int t = blockIdx.x * blockDim.x + threadIdx.x;
    if (t < BB * PADSZ) {
        uint2 v; v.x = 0u; v.y = 0xFF000000u;
        g_pix8[t] = v;
    }
    if (t < NOFF2) g_num[t] = 0.0f;
    if (t == NOFF2)     g_ce = 0.0f;
    if (t == NOFF2 + 1) g_nact = 0;
}

// ---------------- kernel 1: softmax/CE/pack (u8) into padded array -------------
__global__ void k_prep(const float* __restrict__ logit,
                       const float* __restrict__ image,
                       const float* __restrict__ src,
                       const float* __restrict__ dst,
                       const int*   __restrict__ tgt) {
    int idx = blockIdx.x * blockDim.x + threadIdx.x;
    float prod = 0.0f;
    if (idx < HWP) {
        int i = idx / WW;
        int j = idx - i * WW;
        int pidx = (i + SPAN) * PADW + (j + SPAN);
        float Msum = 0.0f, ceSum = 0.0f, dstSum = 0.0f;
#pragma unroll
        for (int b = 0; b < BB; b++) {
            int cb = b * 3 * HWP + idx;
            float l0 = logit[cb], l1 = logit[cb + HWP], l2 = logit[cb + 2 * HWP];
            float m  = fmaxf(l0, fmaxf(l1, l2));
            float e0 = __expf(l0 - m), e1 = __expf(l1 - m), e2 = __expf(l2 - m);
            float s  = e0 + e1 + e2;
            float inv = 1.0f / s;

            int   t  = tgt[b * HWP + idx];
            float lt = (t == 0) ? l0 : ((t == 1) ? l1 : l2);
            float ce = m + __logf(s) - lt;

            float sv   = src[b * HWP + idx];
            float dv   = dst[b * HWP + idx];
            float mdst = 1.0f - dv;

            float i0 = image[cb], i1 = image[cb + HWP], i2 = image[cb + 2 * HWP];
            unsigned r8 = __float2uint_rn(i0 * 255.0f);
            unsigned g8 = __float2uint_rn(i1 * 255.0f);
            unsigned b8 = __float2uint_rn(i2 * 255.0f);

            float y0 = e0 * inv, y1 = e1 * inv;
            int y0q = (int)__float2uint_rn(y0 * 255.0f);
            int y1q = (int)__float2uint_rn(y1 * 255.0f);
            int y2q = 255 - y0q - y1q;
            if (y2q < 0) y2q = 0;

            uint2 v;
            v.x = r8 | (g8 << 8) | (b8 << 16);
            v.y = (unsigned)y0q | ((unsigned)y1q << 8) | ((unsigned)y2q << 16);
            g_pix8[b * PADSZ + pidx] = v;     // byte3 of .y = 0 -> valid
            g_wp[b * HWP + idx] = sv * mdst;

            ceSum  += ce;
            dstSum += dv;
            Msum   += mdst;
        }
        g_M[idx] = Msum;
        prod = ceSum * dstSum;
    }
    float bs = blockReduceSum(prod);
    if (threadIdx.x == 0) atomicAdd(&g_ce, bs);
}

// ---------------- kernel 2: locally-ordered compaction -------------------------
__global__ void k_compact() {
    __shared__ int s_w[8];
    __shared__ int s_base;
    int tid  = threadIdx.x;
    int lane = tid & 31;
    int wid  = tid >> 5;
    int p    = blockIdx.x * 256 + tid;          // < NPIX exactly

    bool a = g_wp[p] > 0.0f;
    unsigned bal = __ballot_sync(0xffffffffu, a);
    if (lane == 0) s_w[wid] = __popc(bal);
    __syncthreads();
    if (tid == 0) {
        int acc = 0;
#pragma unroll
        for (int w = 0; w < 8; w++) { int c = s_w[w]; s_w[w] = acc; acc += c; }
        s_base = atomicAdd(&g_nact, acc);
    }
    __syncthreads();
    if (a) {
        int pos = s_base + s_w[wid] + __popc(bal & ((1u << lane) - 1u));
        int b   = p / HWP;
        int rem = p - b * HWP;
        int i   = rem / WW;
        int j   = rem - i * WW;
        g_act[pos] = b * PADSZ + (i + SPAN) * PADW + (j + SPAN);
    }
}

// ---------------- kernel 3a: row prefix sums (warp per row, register scan) ------
__global__ void k_rps() {               // grid=HH, block=32
    int i = blockIdx.x;
    int l = threadIdx.x;
    float v[15];
    float s = 0.0f;
    const float* row = g_M + i * WW + l * 15;
#pragma unroll
    for (int e = 0; e < 15; e++) { s += row[e]; v[e] = s; }
    // inclusive warp scan of per-lane totals
    float tot = s;
#pragma unroll
    for (int o = 1; o < 32; o <<= 1) {
        float u = __shfl_up_sync(0xffffffffu, tot, o);
        if (l >= o) tot += u;
    }
    float off = tot - s;                 // exclusive prefix for this lane
    if (l == 0) g_rps[i][0] = 0.0f;
    float* orow = &g_rps[i][l * 15 + 1];
#pragma unroll
    for (int e = 0; e < 15; e++) orow[e] = v[e] + off;
}

// ---------------- kernel 3b: denominators (warp per offset) ---------------------
__global__ void k_den() {               // grid=ceil(529/8), block=256
    int w    = (blockIdx.x * 256 + threadIdx.x) >> 5;
    int lane = threadIdx.x & 31;
    if (w >= NOFF2) return;
    int dx = w / NOFF - SPAN;
    int dy = w % NOFF - SPAN;
    int r0 = (dx < 0) ? -dx : 0;
    int r1 = (dx > 0) ? HH - dx : HH;
    int c0 = (dy < 0) ? -dy : 0;
    int c1 = (dy > 0) ? WW - dy : WW;
    float s = 0.0f;
    for (int i = r0 + lane; i < r1; i += 32)
        s += g_rps[i][c1] - g_rps[i][c0];
    float tot = warpReduceSum(s);
    if (lane == 0) g_den[w] = tot;
}

// ---------------- kernel 4: numerators ------------------------------------------
// One dx per blockIdx.y; threads grid-stride the active list holding acc[23],
// reduce ONCE at thread end. Validity is purely arithmetic: halo cells carry
// y = 0xFF000000; p's register y-copy sets byte3=255, so dp4a == 65025 exactly
// for halo q => tv == 0 exactly. No predicates, no bounds checks in the body.
__global__ void __launch_bounds__(256) k_num() {
    __shared__ float s_kxy[NOFF];

    int dxi = blockIdx.y;                       // 0..21
    int dx  = (dxi < SPAN) ? dxi - SPAN : dxi - SPAN + 1;

    if (threadIdx.x < NOFF) {
        int dy = threadIdx.x - SPAN;
        s_kxy[threadIdx.x] = __expf((float)(dx * dx + dy * dy) * (-1.0f / 72.0f));
    }
    __syncthreads();

    float acc[NOFF];
#pragma unroll
    for (int k = 0; k < NOFF; k++) acc[k] = 0.0f;

    const float KC  = (-50.0f / 65025.0f) * 1.44269504088896f;  // exp2 scale for ssd
    const float YC  = 1.0f / 65025.0f;

    int n = g_nact;
    int stride = gridDim.x * 256;
    for (int t = blockIdx.x * 256 + threadIdx.x; t < n; t += stride) {
        int idx = g_act[t];
        uint2 p = g_pix8[idx];
        unsigned py = p.y | 0xFF000000u;        // marker in register copy only
        const uint2* __restrict__ qrow = g_pix8 + (idx + dx * PADW);

#pragma unroll
        for (int k = 0; k < NOFF; k++) {
            if (k == SPAN) continue;            // dy == 0 skipped
            uint2 q = __ldg(qrow + (k - SPAN));
            unsigned d  = __vabsdiffu4(p.x, q.x);
            unsigned s2 = __dp4a(d, d, 0u);
            unsigned dp = __dp4a(py, q.y, 0u);
            float krgb = exp2f(__int2float_rn((int)s2) * KC);
            float tv   = __int2float_rn(65025 - (int)dp) * YC;  // exact 0 for halo
            acc[k] += (krgb + s_kxy[k]) * tv;
        }
    }

    int lane   = threadIdx.x & 31;
    int rowbin = (dx + SPAN) * NOFF;
#pragma unroll
    for (int k = 0; k < NOFF; k++) {
        if (k == SPAN) continue;
        float v = warpReduceSum(acc[k]);
        if (lane == 0) atomicAdd(&g_num[rowbin + k], v);
    }
}

// ---------------- kernel 5: finalize --------------------------------------------
__global__ void k_final(float* __restrict__ out) {
    float s = 0.0f;
    for (int d = threadIdx.x; d < NOFF2; d += blockDim.x) {
        int dx = d / NOFF - SPAN;
        int dy = d % NOFF - SPAN;
        if (dx != 0 && dy != 0) s += g_num[d] / g_den[d];
    }
    float tot = blockReduceSum(s);
    if (threadIdx.x == 0) {
        float l_ce   = g_ce * (1.0f / ((float)BB * BB * HWP));
        float l_gcrf = tot * (1.0f / (float)NOFF2);
        out[0] = l_ce + 0.15f * l_gcrf;
    }
}

// ---------------- launch ----------------------------------------------------------
extern "C" void kernel_launch(void* const* d_in, const int* in_sizes, int n_in,
                              void* d_out, int out_size) {
    const float* logit = (const float*)d_in[0];
    const float* image = (const float*)d_in[1];
    const float* srcm  = (const float*)d_in[2];
    const float* dstm  = (const float*)d_in[3];
    const int*   tgt   = (const int*)d_in[4];
    float* out = (float*)d_out;

    k_zero<<<(BB * PADSZ + 255) / 256, 256>>>();
    k_prep<<<(HWP + 255) / 256, 256>>>(logit, image, srcm, dstm, tgt);
    k_compact<<<NPIX / 256, 256>>>();
    k_rps<<<HH, 32>>>();
    k_den<<<(NOFF2 + 7) / 8, 256>>>();
    k_num<<<dim3(NUMX, 2 * SPAN), 256>>>();
    k_final<<<1, 256>>>(out);
}